// round 1
// baseline (speedup 1.0000x reference)
#include <cuda_runtime.h>
#include <math.h>

// Problem constants (fixed by the dataset: B=2,S=2048,H=2048,E=8,F=2048,top_k=2)
#define T_TOK 4096
#define H_DIM 2048
#define E_NUM 8
#define F_DIM 2048

#define BM 64
#define BN 64
#define BK 16
#define MAX_TILES 144                       // >= sum ceil(cnt_e/64) <= 135
#define MAX_SLOTS (T_TOK * 2 + E_NUM * BM)  // 8704 (8192 slots + per-expert pad)

// ---------------- scratch (static device memory; no allocations allowed) ----
__device__ float g_act[(size_t)MAX_SLOTS * F_DIM];  // SwiGLU activations
__device__ int   g_perm[MAX_SLOTS];                 // slot -> token
__device__ float g_slotw[MAX_SLOTS];                // slot -> combine weight (0 for pad)
__device__ int   g_topi[T_TOK * 2];
__device__ float g_topw[T_TOK * 2];
__device__ int   g_tile_expert[MAX_TILES];
__device__ int   g_ntiles;

// ---------------- zero output ----------------------------------------------
__global__ void zero_kernel(float4* out, int n4) {
    int i = blockIdx.x * blockDim.x + threadIdx.x;
    if (i < n4) out[i] = make_float4(0.f, 0.f, 0.f, 0.f);
}

// ---------------- router: logits -> softmax -> top2 -> renormalized weights -
__global__ void router_kernel(const float* __restrict__ x,
                              const float* __restrict__ gw) {
    int warp = threadIdx.x >> 5, lane = threadIdx.x & 31;
    int t = blockIdx.x * 8 + warp;
    if (t >= T_TOK) return;
    const float* xr = x + (size_t)t * H_DIM;
    float acc[E_NUM];
#pragma unroll
    for (int e = 0; e < E_NUM; e++) acc[e] = 0.f;
    for (int i = lane; i < H_DIM; i += 32) {
        float xv = xr[i];
#pragma unroll
        for (int e = 0; e < E_NUM; e++) acc[e] += xv * gw[e * H_DIM + i];
    }
#pragma unroll
    for (int e = 0; e < E_NUM; e++)
        for (int o = 16; o > 0; o >>= 1)
            acc[e] += __shfl_down_sync(0xffffffffu, acc[e], o);
    if (lane == 0) {
        float m = acc[0];
#pragma unroll
        for (int e = 1; e < E_NUM; e++) m = fmaxf(m, acc[e]);
        float p[E_NUM];
#pragma unroll
        for (int e = 0; e < E_NUM; e++) p[e] = expf(acc[e] - m);
        // top-2 by prob (== by logit); strict > keeps lowest index on ties,
        // matching lax.top_k tie behavior.
        int a = 0;
#pragma unroll
        for (int e = 1; e < E_NUM; e++) if (p[e] > p[a]) a = e;
        int b = (a == 0) ? 1 : 0;
#pragma unroll
        for (int e = 0; e < E_NUM; e++)
            if (e != a && p[e] > p[b]) b = e;
        float denom = p[a] + p[b];
        g_topi[t * 2 + 0] = a;
        g_topi[t * 2 + 1] = b;
        g_topw[t * 2 + 0] = p[a] / denom;  // full-softmax norm cancels
        g_topw[t * 2 + 1] = p[b] / denom;
    }
}

// ---------------- assign: counts, padded offsets, slot permutation ----------
__global__ void assign_kernel() {
    __shared__ int cnt[E_NUM], cur[E_NUM], off[E_NUM], pcnt[E_NUM];
    int tid = threadIdx.x;
    if (tid < E_NUM) { cnt[tid] = 0; cur[tid] = 0; }
    __syncthreads();
    for (int i = tid; i < T_TOK * 2; i += blockDim.x)
        atomicAdd(&cnt[g_topi[i]], 1);
    __syncthreads();
    if (tid == 0) {
        int o = 0, mt = 0;
        for (int e = 0; e < E_NUM; e++) {
            off[e] = o;
            int pc = ((cnt[e] + BM - 1) / BM) * BM;
            pcnt[e] = pc;
            int tiles = pc / BM;
            for (int i = 0; i < tiles; i++) g_tile_expert[mt + i] = e;
            mt += tiles;
            o += pc;
        }
        g_ntiles = mt;
        for (int i = mt; i < MAX_TILES; i++) g_tile_expert[i] = 0;
    }
    __syncthreads();
    for (int i = tid; i < T_TOK * 2; i += blockDim.x) {
        int e = g_topi[i];
        int pos = off[e] + atomicAdd(&cur[e], 1);
        g_perm[pos] = i >> 1;  // token id
        g_slotw[pos] = g_topw[i];
    }
    __syncthreads();
    // fill padding rows (weight 0, token 0)
    for (int j = tid; j < E_NUM * BM; j += blockDim.x) {
        int e = j / BM;
        int i = cnt[e] + (j % BM);
        if (i < pcnt[e]) {
            g_perm[off[e] + i] = 0;
            g_slotw[off[e] + i] = 0.f;
        }
    }
}

// ---------------- GEMM1: gathered X @ {w1,w3} fused with SwiGLU -------------
__global__ __launch_bounds__(256) void gemm1_kernel(const float* __restrict__ x,
                                                    const float* __restrict__ w1,
                                                    const float* __restrict__ w3) {
    int mt = blockIdx.x;
    if (mt >= g_ntiles) return;
    int e = g_tile_expert[mt];
    int m0 = mt * BM, n0 = blockIdx.y * BN;

    __shared__ int   rows[BM];
    __shared__ float As[BK][BM];
    __shared__ float B1s[BK][BN];
    __shared__ float B3s[BK][BN];

    int tid = threadIdx.x;
    if (tid < BM) rows[tid] = g_perm[m0 + tid];
    __syncthreads();

    int tx = tid & 15, ty = tid >> 4;
    int ar = tid >> 2, ac = (tid & 3) * 4;   // A loader: row 0..63, k 0/4/8/12
    int br = tid >> 4, bc = (tid & 15) * 4;  // B loader: k 0..15, n col*4

    const float* w1e = w1 + (size_t)e * H_DIM * F_DIM;
    const float* w3e = w3 + (size_t)e * H_DIM * F_DIM;

    float acc1[4][4], acc3[4][4];
#pragma unroll
    for (int i = 0; i < 4; i++)
#pragma unroll
        for (int j = 0; j < 4; j++) { acc1[i][j] = 0.f; acc3[i][j] = 0.f; }

    for (int k0 = 0; k0 < H_DIM; k0 += BK) {
        float4 av  = *(const float4*)(x + (size_t)rows[ar] * H_DIM + k0 + ac);
        float4 b1v = *(const float4*)(w1e + (size_t)(k0 + br) * F_DIM + n0 + bc);
        float4 b3v = *(const float4*)(w3e + (size_t)(k0 + br) * F_DIM + n0 + bc);
        As[ac + 0][ar] = av.x;
        As[ac + 1][ar] = av.y;
        As[ac + 2][ar] = av.z;
        As[ac + 3][ar] = av.w;
        *(float4*)&B1s[br][bc] = b1v;
        *(float4*)&B3s[br][bc] = b3v;
        __syncthreads();
#pragma unroll
        for (int kk = 0; kk < BK; kk++) {
            float4 a  = *(const float4*)&As[kk][ty * 4];
            float4 b1 = *(const float4*)&B1s[kk][tx * 4];
            float4 b3 = *(const float4*)&B3s[kk][tx * 4];
            float aa[4]  = {a.x, a.y, a.z, a.w};
            float bb1[4] = {b1.x, b1.y, b1.z, b1.w};
            float bb3[4] = {b3.x, b3.y, b3.z, b3.w};
#pragma unroll
            for (int i = 0; i < 4; i++)
#pragma unroll
                for (int j = 0; j < 4; j++) {
                    acc1[i][j] += aa[i] * bb1[j];
                    acc3[i][j] += aa[i] * bb3[j];
                }
        }
        __syncthreads();
    }

#pragma unroll
    for (int i = 0; i < 4; i++) {
        int r = m0 + ty * 4 + i;
        float4 o;
        float h1, h3, sg;
        h1 = acc1[i][0]; h3 = acc3[i][0]; sg = 1.f / (1.f + __expf(-h1)); o.x = h1 * sg * h3;
        h1 = acc1[i][1]; h3 = acc3[i][1]; sg = 1.f / (1.f + __expf(-h1)); o.y = h1 * sg * h3;
        h1 = acc1[i][2]; h3 = acc3[i][2]; sg = 1.f / (1.f + __expf(-h1)); o.z = h1 * sg * h3;
        h1 = acc1[i][3]; h3 = acc3[i][3]; sg = 1.f / (1.f + __expf(-h1)); o.w = h1 * sg * h3;
        *(float4*)&g_act[(size_t)r * F_DIM + n0 + tx * 4] = o;
    }
}

// ---------------- GEMM2: act @ w2 + weighted scatter-add into out -----------
__global__ __launch_bounds__(256) void gemm2_kernel(const float* __restrict__ w2,
                                                    float* __restrict__ out) {
    int mt = blockIdx.x;
    if (mt >= g_ntiles) return;
    int e = g_tile_expert[mt];
    int m0 = mt * BM, n0 = blockIdx.y * BN;

    __shared__ int   rows[BM];
    __shared__ float ws[BM];
    __shared__ float As[BK][BM];
    __shared__ float Bs[BK][BN];

    int tid = threadIdx.x;
    if (tid < BM) {
        rows[tid] = g_perm[m0 + tid];
        ws[tid]   = g_slotw[m0 + tid];
    }
    __syncthreads();

    int tx = tid & 15, ty = tid >> 4;
    int ar = tid >> 2, ac = (tid & 3) * 4;
    int br = tid >> 4, bc = (tid & 15) * 4;

    const float* w2e = w2 + (size_t)e * F_DIM * H_DIM;

    float acc[4][4];
#pragma unroll
    for (int i = 0; i < 4; i++)
#pragma unroll
        for (int j = 0; j < 4; j++) acc[i][j] = 0.f;

    for (int k0 = 0; k0 < F_DIM; k0 += BK) {
        float4 av = *(const float4*)(g_act + (size_t)(m0 + ar) * F_DIM + k0 + ac);
        float4 bv = *(const float4*)(w2e + (size_t)(k0 + br) * H_DIM + n0 + bc);
        As[ac + 0][ar] = av.x;
        As[ac + 1][ar] = av.y;
        As[ac + 2][ar] = av.z;
        As[ac + 3][ar] = av.w;
        *(float4*)&Bs[br][bc] = bv;
        __syncthreads();
#pragma unroll
        for (int kk = 0; kk < BK; kk++) {
            float4 a = *(const float4*)&As[kk][ty * 4];
            float4 b = *(const float4*)&Bs[kk][tx * 4];
            float aa[4] = {a.x, a.y, a.z, a.w};
            float bb[4] = {b.x, b.y, b.z, b.w};
#pragma unroll
            for (int i = 0; i < 4; i++)
#pragma unroll
                for (int j = 0; j < 4; j++) acc[i][j] += aa[i] * bb[j];
        }
        __syncthreads();
    }

#pragma unroll
    for (int i = 0; i < 4; i++) {
        int r = ty * 4 + i;
        float w = ws[r];
        if (w != 0.f) {
            size_t base = (size_t)rows[r] * H_DIM + n0 + tx * 4;
#pragma unroll
            for (int j = 0; j < 4; j++)
                atomicAdd(&out[base + j], w * acc[i][j]);
        }
    }
}

// ---------------- launch ----------------------------------------------------
extern "C" void kernel_launch(void* const* d_in, const int* in_sizes, int n_in,
                              void* d_out, int out_size) {
    const float* x  = (const float*)d_in[0];  // hidden_states [2,2048,2048]
    const float* gw = (const float*)d_in[1];  // gate_w  [8,2048]
    const float* w1 = (const float*)d_in[2];  // w1s [8,2048,2048]
    const float* w2 = (const float*)d_in[3];  // w2s [8,2048,2048]
    const float* w3 = (const float*)d_in[4];  // w3s [8,2048,2048]
    float* out = (float*)d_out;

    int n4 = (T_TOK * H_DIM) / 4;
    zero_kernel<<<(n4 + 255) / 256, 256>>>((float4*)out, n4);
    router_kernel<<<T_TOK / 8, 256>>>(x, gw);
    assign_kernel<<<1, 256>>>();

    dim3 g1(MAX_TILES, F_DIM / BN);
    gemm1_kernel<<<g1, 256>>>(x, w1, w3);

    dim3 g2(MAX_TILES, H_DIM / BN);
    gemm2_kernel<<<g2, 256>>>(w2, out);
}

// round 3
// speedup vs baseline: 1.8188x; 1.8188x over previous
#include <cuda_runtime.h>
#include <cuda_fp16.h>
#include <math.h>
#include <stdint.h>

// Problem constants: B=2,S=2048,H=2048,E=8,F=2048,top_k=2 (fp32 in/out)
#define T_TOK 4096
#define H_DIM 2048
#define E_NUM 8
#define F_DIM 2048

#define BM 128
#define MAX_TILES 72
#define MAX_SLOTS (T_TOK * 2 + E_NUM * BM)  // 9216
#define NSTAGE 64                            // K/32

// ---------------- static device scratch (fp16 hi/lo splits) -----------------
__device__ __half g_xhi[(size_t)T_TOK * H_DIM];
__device__ __half g_xlo[(size_t)T_TOK * H_DIM];
__device__ __half g_w1hi[(size_t)E_NUM * H_DIM * F_DIM];  // same [E][H][F] layout
__device__ __half g_w1lo[(size_t)E_NUM * H_DIM * F_DIM];
__device__ __half g_w3hi[(size_t)E_NUM * H_DIM * F_DIM];
__device__ __half g_w3lo[(size_t)E_NUM * H_DIM * F_DIM];
__device__ __half g_w2hi[(size_t)E_NUM * F_DIM * H_DIM];  // [E][F][H]
__device__ __half g_w2lo[(size_t)E_NUM * F_DIM * H_DIM];
__device__ __half g_acthi[(size_t)MAX_SLOTS * F_DIM];
__device__ __half g_actlo[(size_t)MAX_SLOTS * F_DIM];

__device__ int   g_perm[MAX_SLOTS];
__device__ float g_slotw[MAX_SLOTS];
__device__ int   g_topi[T_TOK * 2];
__device__ float g_topw[T_TOK * 2];
__device__ int   g_tile_expert[MAX_TILES];
__device__ int   g_ntiles;

// ---------------- PTX helpers (all plain compute_103-legal) -----------------
__device__ __forceinline__ uint32_t smem_u32(const void* p) {
    uint32_t a;
    asm("{ .reg .u64 t; cvta.to.shared.u64 t, %1; cvt.u32.u64 %0, t; }" : "=r"(a) : "l"(p));
    return a;
}
__device__ __forceinline__ void cpa(uint32_t dst, const void* src) {
    asm volatile("cp.async.cg.shared.global [%0], [%1], 16;" :: "r"(dst), "l"(src));
}
#define CP_COMMIT() asm volatile("cp.async.commit_group;" ::: "memory")
#define CP_WAIT1()  asm volatile("cp.async.wait_group 1;" ::: "memory")

__device__ __forceinline__ void ldsm4(uint32_t* r, uint32_t addr) {
    asm volatile("ldmatrix.sync.aligned.m8n8.x4.shared.b16 {%0,%1,%2,%3}, [%4];"
                 : "=r"(r[0]), "=r"(r[1]), "=r"(r[2]), "=r"(r[3]) : "r"(addr));
}
__device__ __forceinline__ void ldsm4t(uint32_t* r, uint32_t addr) {
    asm volatile("ldmatrix.sync.aligned.m8n8.x4.trans.shared.b16 {%0,%1,%2,%3}, [%4];"
                 : "=r"(r[0]), "=r"(r[1]), "=r"(r[2]), "=r"(r[3]) : "r"(addr));
}
__device__ __forceinline__ void mma16816(float* d, const uint32_t* a, const uint32_t* b) {
    asm volatile(
        "mma.sync.aligned.m16n8k16.row.col.f32.f16.f16.f32 "
        "{%0,%1,%2,%3}, {%4,%5,%6,%7}, {%8,%9}, {%0,%1,%2,%3};"
        : "+f"(d[0]), "+f"(d[1]), "+f"(d[2]), "+f"(d[3])
        : "r"(a[0]), "r"(a[1]), "r"(a[2]), "r"(a[3]), "r"(b[0]), "r"(b[1]));
}

__device__ __forceinline__ void split2(float a, float b, uint32_t& h, uint32_t& l) {
    __half ha = __float2half_rn(a), hb = __float2half_rn(b);
    __half la = __float2half_rn(a - __half2float(ha));
    __half lb = __float2half_rn(b - __half2float(hb));
    h = (uint32_t)__half_as_ushort(ha) | ((uint32_t)__half_as_ushort(hb) << 16);
    l = (uint32_t)__half_as_ushort(la) | ((uint32_t)__half_as_ushort(lb) << 16);
}

// ---------------- zero output ----------------------------------------------
__global__ void zero_kernel(float4* out, int n4) {
    int i = blockIdx.x * blockDim.x + threadIdx.x;
    if (i < n4) out[i] = make_float4(0.f, 0.f, 0.f, 0.f);
}

// ---------------- router ---------------------------------------------------
__global__ void router_kernel(const float* __restrict__ x,
                              const float* __restrict__ gw) {
    int warp = threadIdx.x >> 5, lane = threadIdx.x & 31;
    int t = blockIdx.x * 8 + warp;
    if (t >= T_TOK) return;
    const float* xr = x + (size_t)t * H_DIM;
    float acc[E_NUM];
#pragma unroll
    for (int e = 0; e < E_NUM; e++) acc[e] = 0.f;
    for (int i = lane; i < H_DIM; i += 32) {
        float xv = xr[i];
#pragma unroll
        for (int e = 0; e < E_NUM; e++) acc[e] += xv * gw[e * H_DIM + i];
    }
#pragma unroll
    for (int e = 0; e < E_NUM; e++)
        for (int o = 16; o > 0; o >>= 1)
            acc[e] += __shfl_down_sync(0xffffffffu, acc[e], o);
    if (lane == 0) {
        float m = acc[0];
#pragma unroll
        for (int e = 1; e < E_NUM; e++) m = fmaxf(m, acc[e]);
        float p[E_NUM];
#pragma unroll
        for (int e = 0; e < E_NUM; e++) p[e] = expf(acc[e] - m);
        int a = 0;
#pragma unroll
        for (int e = 1; e < E_NUM; e++) if (p[e] > p[a]) a = e;
        int b = (a == 0) ? 1 : 0;
#pragma unroll
        for (int e = 0; e < E_NUM; e++)
            if (e != a && p[e] > p[b]) b = e;
        float denom = p[a] + p[b];
        g_topi[t * 2 + 0] = a;
        g_topi[t * 2 + 1] = b;
        g_topw[t * 2 + 0] = p[a] / denom;
        g_topw[t * 2 + 1] = p[b] / denom;
    }
}

// ---------------- assign ----------------------------------------------------
__global__ void assign_kernel() {
    __shared__ int cnt[E_NUM], cur[E_NUM], off[E_NUM], pcnt[E_NUM];
    int tid = threadIdx.x;
    if (tid < E_NUM) { cnt[tid] = 0; cur[tid] = 0; }
    __syncthreads();
    for (int i = tid; i < T_TOK * 2; i += blockDim.x)
        atomicAdd(&cnt[g_topi[i]], 1);
    __syncthreads();
    if (tid == 0) {
        int o = 0, mt = 0;
        for (int e = 0; e < E_NUM; e++) {
            off[e] = o;
            int pc = ((cnt[e] + BM - 1) / BM) * BM;
            pcnt[e] = pc;
            int tiles = pc / BM;
            for (int i = 0; i < tiles; i++) g_tile_expert[mt + i] = e;
            mt += tiles;
            o += pc;
        }
        g_ntiles = mt;
        for (int i = mt; i < MAX_TILES; i++) g_tile_expert[i] = 0;
    }
    __syncthreads();
    for (int i = tid; i < T_TOK * 2; i += blockDim.x) {
        int e = g_topi[i];
        int pos = off[e] + atomicAdd(&cur[e], 1);
        g_perm[pos] = i >> 1;
        g_slotw[pos] = g_topw[i];
    }
    __syncthreads();
    for (int j = tid; j < E_NUM * BM; j += blockDim.x) {
        int e = j / BM;
        int i = cnt[e] + (j % BM);
        if (i < pcnt[e]) {
            g_perm[off[e] + i] = 0;
            g_slotw[off[e] + i] = 0.f;
        }
    }
}

// ---------------- fp32 -> fp16 hi/lo, elementwise (no transpose) ------------
__global__ void convert_kernel(const float* __restrict__ src, int which) {
    size_t i = (size_t)blockIdx.x * blockDim.x + threadIdx.x;  // float4 index
    __half *oh, *ol;
    if (which == 0)      { oh = g_xhi;  ol = g_xlo;  }
    else if (which == 1) { oh = g_w1hi; ol = g_w1lo; }
    else if (which == 2) { oh = g_w3hi; ol = g_w3lo; }
    else                 { oh = g_w2hi; ol = g_w2lo; }
    float4 v = ((const float4*)src)[i];
    uint32_t h0, l0, h1, l1;
    split2(v.x, v.y, h0, l0);
    split2(v.z, v.w, h1, l1);
    ((uint2*)oh)[i] = make_uint2(h0, h1);
    ((uint2*)ol)[i] = make_uint2(l0, l1);
}

// ============================================================================
// GEMM1: gathered x[slot,:] @ {w1,w3} -> SwiGLU -> act hi/lo
// BM=128, BN=64 (per matrix), BK=32, 8 warps (4m x 2n), 3-stage cp.async
// SMEM: rows[128] @0 | stage buf: Ahi(10240) Alo(10240) B[mat][hl](4608 ea)
// ============================================================================
#define G1_STAGE 38912
#define G1_SMEM (512 + 3 * G1_STAGE)

__global__ __launch_bounds__(256, 1) void gemm1_kernel() {
    const int mt = blockIdx.y;
    if (mt >= g_ntiles) return;
    extern __shared__ char smem[];
    int* rows = (int*)smem;
    const uint32_t sb = smem_u32(smem);
    const int tid = threadIdx.x;
    const int lane = tid & 31, wid = tid >> 5;
    const int e = g_tile_expert[mt];
    const int m0 = mt * BM;
    const int n0 = blockIdx.x * 64;

    if (tid < 128) rows[tid] = g_perm[m0 + tid];
    __syncthreads();

    // ---- loader state ----
    const int ar = tid >> 1, ac0 = (tid & 1) * 2;  // A: row, chunk base
    const __half* srcAh = g_xhi + (size_t)rows[ar] * H_DIM + ac0 * 8;
    const __half* srcAl = g_xlo + (size_t)rows[ar] * H_DIM + ac0 * 8;
    const int sel = tid >> 6;                     // B: 0..3 -> (mat,hl)
    const int krow = tid & 31, chalf = (tid >> 5) & 1;
    const __half* wsrc0[4] = {
        g_w1hi + (size_t)e * H_DIM * F_DIM, g_w1lo + (size_t)e * H_DIM * F_DIM,
        g_w3hi + (size_t)e * H_DIM * F_DIM, g_w3lo + (size_t)e * H_DIM * F_DIM};
    const __half* srcB = wsrc0[sel] + (size_t)krow * F_DIM + n0 + chalf * 32;
    const uint32_t dstA_h = (uint32_t)(ar * 80 + ac0 * 16);
    const uint32_t dstB = 20480u + (uint32_t)sel * 4608u + (uint32_t)(krow * 144 + chalf * 64);

    const int warpm = wid & 3, warpn = wid >> 2;
    const int m0w = warpm * 32, n0w = warpn * 32;

    float acc1[2][4][4], acc3[2][4][4];
#pragma unroll
    for (int mi = 0; mi < 2; mi++)
#pragma unroll
        for (int ni = 0; ni < 4; ni++)
#pragma unroll
            for (int r = 0; r < 4; r++) { acc1[mi][ni][r] = 0.f; acc3[mi][ni][r] = 0.f; }

#define G1_ISSUE(p)                                                              \
    {                                                                            \
        uint32_t st = sb + 512 + (uint32_t)((p) % 3) * G1_STAGE;                 \
        size_t k0 = (size_t)(p) * 32;                                            \
        cpa(st + dstA_h, srcAh + k0);                                            \
        cpa(st + dstA_h + 16, srcAh + k0 + 8);                                   \
        cpa(st + 10240 + dstA_h, srcAl + k0);                                    \
        cpa(st + 10240 + dstA_h + 16, srcAl + k0 + 8);                           \
        const __half* bs = srcB + k0 * F_DIM;                                    \
        cpa(st + dstB, bs);                                                      \
        cpa(st + dstB + 16, bs + 8);                                             \
        cpa(st + dstB + 32, bs + 16);                                            \
        cpa(st + dstB + 48, bs + 24);                                            \
    }

    G1_ISSUE(0); CP_COMMIT();
    G1_ISSUE(1); CP_COMMIT();

    // per-lane ldmatrix address components
    const int a_lrow = (lane < 16) ? lane : (lane - 16);
    const int a_lkoff = (lane >= 16) ? 8 : 0;
    const int b_lk = ((lane >> 3) & 1) * 8 + (lane & 7);
    const int b_ln = (lane >> 4) * 8;

    for (int s = 0; s < NSTAGE; s++) {
        CP_WAIT1();
        __syncthreads();
        if (s + 2 < NSTAGE) { G1_ISSUE(s + 2); }
        CP_COMMIT();

        const uint32_t st = sb + 512 + (uint32_t)(s % 3) * G1_STAGE;
#pragma unroll
        for (int k16 = 0; k16 < 2; k16++) {
            const int kl = k16 * 16;
            uint32_t ahi[2][4], alo[2][4];
#pragma unroll
            for (int mi = 0; mi < 2; mi++) {
                uint32_t aaddr = st + (uint32_t)((m0w + mi * 16 + a_lrow) * 80 + (kl + a_lkoff) * 2);
                ldsm4(ahi[mi], aaddr);
                ldsm4(alo[mi], aaddr + 10240);
            }
            uint32_t B[2][2][4][2];  // [mat][hl][ni][reg]
#pragma unroll
            for (int mat = 0; mat < 2; mat++)
#pragma unroll
                for (int hl = 0; hl < 2; hl++)
#pragma unroll
                    for (int nh = 0; nh < 2; nh++) {
                        uint32_t baddr = st + 20480u + (uint32_t)(mat * 2 + hl) * 4608u +
                                         (uint32_t)((kl + b_lk) * 144 + (n0w + nh * 16 + b_ln) * 2);
                        uint32_t tmp[4];
                        ldsm4t(tmp, baddr);
                        B[mat][hl][nh * 2 + 0][0] = tmp[0];
                        B[mat][hl][nh * 2 + 0][1] = tmp[1];
                        B[mat][hl][nh * 2 + 1][0] = tmp[2];
                        B[mat][hl][nh * 2 + 1][1] = tmp[3];
                    }
#pragma unroll
            for (int mi = 0; mi < 2; mi++)
#pragma unroll
                for (int ni = 0; ni < 4; ni++) {
                    mma16816(acc1[mi][ni], ahi[mi], B[0][0][ni]);
                    mma16816(acc1[mi][ni], ahi[mi], B[0][1][ni]);
                    mma16816(acc1[mi][ni], alo[mi], B[0][0][ni]);
                    mma16816(acc3[mi][ni], ahi[mi], B[1][0][ni]);
                    mma16816(acc3[mi][ni], ahi[mi], B[1][1][ni]);
                    mma16816(acc3[mi][ni], alo[mi], B[1][0][ni]);
                }
        }
        __syncthreads();
    }

    // epilogue: SwiGLU + split -> act hi/lo
    const int g = lane >> 2, tq = lane & 3;
#pragma unroll
    for (int mi = 0; mi < 2; mi++)
#pragma unroll
        for (int rp = 0; rp < 2; rp++) {
            const int slot = m0 + m0w + mi * 16 + rp * 8 + g;
#pragma unroll
            for (int ni = 0; ni < 4; ni++) {
                float h1a = acc1[mi][ni][rp * 2 + 0], h1b = acc1[mi][ni][rp * 2 + 1];
                float h3a = acc3[mi][ni][rp * 2 + 0], h3b = acc3[mi][ni][rp * 2 + 1];
                float va = h1a * h3a / (1.f + __expf(-h1a));
                float vb = h1b * h3b / (1.f + __expf(-h1b));
                uint32_t ph, pl;
                split2(va, vb, ph, pl);
                size_t o = (size_t)slot * F_DIM + n0 + n0w + ni * 8 + tq * 2;
                *(uint32_t*)((char*)g_acthi + o * 2) = ph;
                *(uint32_t*)((char*)g_actlo + o * 2) = pl;
            }
        }
}

// ============================================================================
// GEMM2: act @ w2 + weighted scatter-add. BM=128, BN=128, BK=32
// SMEM: rows[128]|ws[128] @0..1024 | stage: Ahi(10240) Alo(10240) B[hl](8704)
// ============================================================================
#define G2_STAGE 37888
#define G2_SMEM (1024 + 3 * G2_STAGE)

__global__ __launch_bounds__(256, 1) void gemm2_kernel(float* __restrict__ out) {
    const int mt = blockIdx.y;
    if (mt >= g_ntiles) return;
    extern __shared__ char smem[];
    int* rows = (int*)smem;
    float* ws = (float*)(smem + 512);
    const uint32_t sb = smem_u32(smem);
    const int tid = threadIdx.x;
    const int lane = tid & 31, wid = tid >> 5;
    const int e = g_tile_expert[mt];
    const int m0 = mt * BM;
    const int n0 = blockIdx.x * 128;

    if (tid < 128) {
        rows[tid] = g_perm[m0 + tid];
        ws[tid] = g_slotw[m0 + tid];
    }
    __syncthreads();

    const int ar = tid >> 1, ac0 = (tid & 1) * 2;
    const __half* srcAh = g_acthi + (size_t)(m0 + ar) * F_DIM + ac0 * 8;
    const __half* srcAl = g_actlo + (size_t)(m0 + ar) * F_DIM + ac0 * 8;
    const int hl = tid >> 7;
    const int krow = tid & 31, cq = (tid >> 5) & 3;
    const __half* w2base = (hl ? g_w2lo : g_w2hi) + (size_t)e * F_DIM * H_DIM;
    const __half* srcB = w2base + (size_t)krow * H_DIM + n0 + cq * 32;
    const uint32_t dstA_h = (uint32_t)(ar * 80 + ac0 * 16);
    const uint32_t dstB = 20480u + (uint32_t)hl * 8704u + (uint32_t)(krow * 272 + cq * 64);

    const int warpm = wid & 3, warpn = wid >> 2;
    const int m0w = warpm * 32, n0w = warpn * 64;

    float acc[2][8][4];
#pragma unroll
    for (int mi = 0; mi < 2; mi++)
#pragma unroll
        for (int ni = 0; ni < 8; ni++)
#pragma unroll
            for (int r = 0; r < 4; r++) acc[mi][ni][r] = 0.f;

#define G2_ISSUE(p)                                                              \
    {                                                                            \
        uint32_t st = sb + 1024 + (uint32_t)((p) % 3) * G2_STAGE;                \
        size_t k0 = (size_t)(p) * 32;                                            \
        cpa(st + dstA_h, srcAh + k0);                                            \
        cpa(st + dstA_h + 16, srcAh + k0 + 8);                                   \
        cpa(st + 10240 + dstA_h, srcAl + k0);                                    \
        cpa(st + 10240 + dstA_h + 16, srcAl + k0 + 8);                           \
        const __half* bs = srcB + k0 * H_DIM;                                    \
        cpa(st + dstB, bs);                                                      \
        cpa(st + dstB + 16, bs + 8);                                             \
        cpa(st + dstB + 32, bs + 16);                                            \
        cpa(st + dstB + 48, bs + 24);                                            \
    }

    G2_ISSUE(0); CP_COMMIT();
    G2_ISSUE(1); CP_COMMIT();

    const int a_lrow = (lane < 16) ? lane : (lane - 16);
    const int a_lkoff = (lane >= 16) ? 8 : 0;
    const int b_lk = ((lane >> 3) & 1) * 8 + (lane & 7);
    const int b_ln = (lane >> 4) * 8;

    for (int s = 0; s < NSTAGE; s++) {
        CP_WAIT1();
        __syncthreads();
        if (s + 2 < NSTAGE) { G2_ISSUE(s + 2); }
        CP_COMMIT();

        const uint32_t st = sb + 1024 + (uint32_t)(s % 3) * G2_STAGE;
#pragma unroll
        for (int k16 = 0; k16 < 2; k16++) {
            const int kl = k16 * 16;
            uint32_t ahi[2][4], alo[2][4];
#pragma unroll
            for (int mi = 0; mi < 2; mi++) {
                uint32_t aaddr = st + (uint32_t)((m0w + mi * 16 + a_lrow) * 80 + (kl + a_lkoff) * 2);
                ldsm4(ahi[mi], aaddr);
                ldsm4(alo[mi], aaddr + 10240);
            }
            uint32_t B[2][8][2];  // [hl][ni][reg]
#pragma unroll
            for (int h = 0; h < 2; h++)
#pragma unroll
                for (int nh = 0; nh < 4; nh++) {
                    uint32_t baddr = st + 20480u + (uint32_t)h * 8704u +
                                     (uint32_t)((kl + b_lk) * 272 + (n0w + nh * 16 + b_ln) * 2);
                    uint32_t tmp[4];
                    ldsm4t(tmp, baddr);
                    B[h][nh * 2 + 0][0] = tmp[0];
                    B[h][nh * 2 + 0][1] = tmp[1];
                    B[h][nh * 2 + 1][0] = tmp[2];
                    B[h][nh * 2 + 1][1] = tmp[3];
                }
#pragma unroll
            for (int mi = 0; mi < 2; mi++)
#pragma unroll
                for (int ni = 0; ni < 8; ni++) {
                    mma16816(acc[mi][ni], ahi[mi], B[0][ni]);
                    mma16816(acc[mi][ni], ahi[mi], B[1][ni]);
                    mma16816(acc[mi][ni], alo[mi], B[0][ni]);
                }
        }
        __syncthreads();
    }

    // epilogue: weighted scatter-add
    const int g = lane >> 2, tq = lane & 3;
#pragma unroll
    for (int mi = 0; mi < 2; mi++)
#pragma unroll
        for (int rp = 0; rp < 2; rp++) {
            const int rloc = m0w + mi * 16 + rp * 8 + g;
            const int tok = rows[rloc];
            const float wt = ws[rloc];
            if (wt != 0.f) {
                float* dst = out + (size_t)tok * H_DIM + n0 + n0w + tq * 2;
#pragma unroll
                for (int ni = 0; ni < 8; ni++) {
                    atomicAdd(dst + ni * 8 + 0, wt * acc[mi][ni][rp * 2 + 0]);
                    atomicAdd(dst + ni * 8 + 1, wt * acc[mi][ni][rp * 2 + 1]);
                }
            }
        }
}

// ---------------- launch ----------------------------------------------------
extern "C" void kernel_launch(void* const* d_in, const int* in_sizes, int n_in,
                              void* d_out, int out_size) {
    const float* x  = (const float*)d_in[0];
    const float* gw = (const float*)d_in[1];
    const float* w1 = (const float*)d_in[2];
    const float* w2 = (const float*)d_in[3];
    const float* w3 = (const float*)d_in[4];
    float* out = (float*)d_out;

    cudaFuncSetAttribute(gemm1_kernel, cudaFuncAttributeMaxDynamicSharedMemorySize, G1_SMEM);
    cudaFuncSetAttribute(gemm2_kernel, cudaFuncAttributeMaxDynamicSharedMemorySize, G2_SMEM);

    int n4 = (T_TOK * H_DIM) / 4;
    zero_kernel<<<(n4 + 255) / 256, 256>>>((float4*)out, n4);
    router_kernel<<<T_TOK / 8, 256>>>(x, gw);
    assign_kernel<<<1, 256>>>();

    convert_kernel<<<(T_TOK * H_DIM / 4) / 256, 256>>>(x, 0);
    int wblocks = (E_NUM * (int)(H_DIM / 4) * (F_DIM / 256));  // 8*512*8 = 32768
    convert_kernel<<<wblocks, 256>>>(w1, 1);
    convert_kernel<<<wblocks, 256>>>(w3, 2);
    convert_kernel<<<wblocks, 256>>>(w2, 3);

    dim3 g1(F_DIM / 64, MAX_TILES);
    gemm1_kernel<<<g1, 256, G1_SMEM>>>();
    dim3 g2(H_DIM / 128, MAX_TILES);
    gemm2_kernel<<<g2, 256, G2_SMEM>>>(out);
}

// round 4
// speedup vs baseline: 2.7486x; 1.5112x over previous
#include <cuda_runtime.h>
#include <cuda_fp16.h>
#include <math.h>
#include <stdint.h>

// Problem constants: B=2,S=2048,H=2048,E=8,F=2048,top_k=2 (fp32 in/out)
#define T_TOK 4096
#define H_DIM 2048
#define E_NUM 8
#define F_DIM 2048

#define BM 128
#define MAX_TILES 72
#define MAX_SLOTS (T_TOK * 2 + E_NUM * BM)  // 9216
#define NSTAGE 64                            // K/32

// ---------------- static device scratch -------------------------------------
// x and act keep hi+lo (A-side split retained); weights keep hi only.
__device__ __half g_xhi[(size_t)T_TOK * H_DIM];
__device__ __half g_xlo[(size_t)T_TOK * H_DIM];
__device__ __half g_w1hi[(size_t)E_NUM * H_DIM * F_DIM];  // [E][H][F]
__device__ __half g_w3hi[(size_t)E_NUM * H_DIM * F_DIM];
__device__ __half g_w2hi[(size_t)E_NUM * F_DIM * H_DIM];  // [E][F][H]
__device__ __half g_acthi[(size_t)MAX_SLOTS * F_DIM];
__device__ __half g_actlo[(size_t)MAX_SLOTS * F_DIM];

__device__ int   g_perm[MAX_SLOTS];
__device__ float g_slotw[MAX_SLOTS];
__device__ int   g_topi[T_TOK * 2];
__device__ float g_topw[T_TOK * 2];
__device__ int   g_tile_expert[MAX_TILES];
__device__ int   g_ntiles;

// ---------------- PTX helpers (plain compute_103-legal) ---------------------
__device__ __forceinline__ uint32_t smem_u32(const void* p) {
    uint32_t a;
    asm("{ .reg .u64 t; cvta.to.shared.u64 t, %1; cvt.u32.u64 %0, t; }" : "=r"(a) : "l"(p));
    return a;
}
__device__ __forceinline__ void cpa(uint32_t dst, const void* src) {
    asm volatile("cp.async.cg.shared.global [%0], [%1], 16;" :: "r"(dst), "l"(src));
}
#define CP_COMMIT() asm volatile("cp.async.commit_group;" ::: "memory")
#define CP_WAIT2()  asm volatile("cp.async.wait_group 2;" ::: "memory")

__device__ __forceinline__ void ldsm4(uint32_t* r, uint32_t addr) {
    asm volatile("ldmatrix.sync.aligned.m8n8.x4.shared.b16 {%0,%1,%2,%3}, [%4];"
                 : "=r"(r[0]), "=r"(r[1]), "=r"(r[2]), "=r"(r[3]) : "r"(addr));
}
__device__ __forceinline__ void ldsm4t(uint32_t* r, uint32_t addr) {
    asm volatile("ldmatrix.sync.aligned.m8n8.x4.trans.shared.b16 {%0,%1,%2,%3}, [%4];"
                 : "=r"(r[0]), "=r"(r[1]), "=r"(r[2]), "=r"(r[3]) : "r"(addr));
}
__device__ __forceinline__ void mma16816(float* d, const uint32_t* a, const uint32_t* b) {
    asm volatile(
        "mma.sync.aligned.m16n8k16.row.col.f32.f16.f16.f32 "
        "{%0,%1,%2,%3}, {%4,%5,%6,%7}, {%8,%9}, {%0,%1,%2,%3};"
        : "+f"(d[0]), "+f"(d[1]), "+f"(d[2]), "+f"(d[3])
        : "r"(a[0]), "r"(a[1]), "r"(a[2]), "r"(a[3]), "r"(b[0]), "r"(b[1]));
}

__device__ __forceinline__ void split2(float a, float b, uint32_t& h, uint32_t& l) {
    __half ha = __float2half_rn(a), hb = __float2half_rn(b);
    __half la = __float2half_rn(a - __half2float(ha));
    __half lb = __float2half_rn(b - __half2float(hb));
    h = (uint32_t)__half_as_ushort(ha) | ((uint32_t)__half_as_ushort(hb) << 16);
    l = (uint32_t)__half_as_ushort(la) | ((uint32_t)__half_as_ushort(lb) << 16);
}

// ---------------- zero output ----------------------------------------------
__global__ void zero_kernel(float4* out, int n4) {
    int i = blockIdx.x * blockDim.x + threadIdx.x;
    if (i < n4) out[i] = make_float4(0.f, 0.f, 0.f, 0.f);
}

// ---------------- router ---------------------------------------------------
__global__ void router_kernel(const float* __restrict__ x,
                              const float* __restrict__ gw) {
    int warp = threadIdx.x >> 5, lane = threadIdx.x & 31;
    int t = blockIdx.x * 8 + warp;
    if (t >= T_TOK) return;
    const float* xr = x + (size_t)t * H_DIM;
    float acc[E_NUM];
#pragma unroll
    for (int e = 0; e < E_NUM; e++) acc[e] = 0.f;
    for (int i = lane; i < H_DIM; i += 32) {
        float xv = xr[i];
#pragma unroll
        for (int e = 0; e < E_NUM; e++) acc[e] += xv * gw[e * H_DIM + i];
    }
#pragma unroll
    for (int e = 0; e < E_NUM; e++)
        for (int o = 16; o > 0; o >>= 1)
            acc[e] += __shfl_down_sync(0xffffffffu, acc[e], o);
    if (lane == 0) {
        float m = acc[0];
#pragma unroll
        for (int e = 1; e < E_NUM; e++) m = fmaxf(m, acc[e]);
        float p[E_NUM];
#pragma unroll
        for (int e = 0; e < E_NUM; e++) p[e] = expf(acc[e] - m);
        int a = 0;
#pragma unroll
        for (int e = 1; e < E_NUM; e++) if (p[e] > p[a]) a = e;
        int b = (a == 0) ? 1 : 0;
#pragma unroll
        for (int e = 0; e < E_NUM; e++)
            if (e != a && p[e] > p[b]) b = e;
        float denom = p[a] + p[b];
        g_topi[t * 2 + 0] = a;
        g_topi[t * 2 + 1] = b;
        g_topw[t * 2 + 0] = p[a] / denom;
        g_topw[t * 2 + 1] = p[b] / denom;
    }
}

// ---------------- assign ----------------------------------------------------
__global__ void assign_kernel() {
    __shared__ int cnt[E_NUM], cur[E_NUM], off[E_NUM], pcnt[E_NUM];
    int tid = threadIdx.x;
    if (tid < E_NUM) { cnt[tid] = 0; cur[tid] = 0; }
    __syncthreads();
    for (int i = tid; i < T_TOK * 2; i += blockDim.x)
        atomicAdd(&cnt[g_topi[i]], 1);
    __syncthreads();
    if (tid == 0) {
        int o = 0, mt = 0;
        for (int e = 0; e < E_NUM; e++) {
            off[e] = o;
            int pc = ((cnt[e] + BM - 1) / BM) * BM;
            pcnt[e] = pc;
            int tiles = pc / BM;
            for (int i = 0; i < tiles; i++) g_tile_expert[mt + i] = e;
            mt += tiles;
            o += pc;
        }
        g_ntiles = mt;
        for (int i = mt; i < MAX_TILES; i++) g_tile_expert[i] = 0;
    }
    __syncthreads();
    for (int i = tid; i < T_TOK * 2; i += blockDim.x) {
        int e = g_topi[i];
        int pos = off[e] + atomicAdd(&cur[e], 1);
        g_perm[pos] = i >> 1;
        g_slotw[pos] = g_topw[i];
    }
    __syncthreads();
    for (int j = tid; j < E_NUM * BM; j += blockDim.x) {
        int e = j / BM;
        int i = cnt[e] + (j % BM);
        if (i < pcnt[e]) {
            g_perm[off[e] + i] = 0;
            g_slotw[off[e] + i] = 0.f;
        }
    }
}

// ---------------- unified conversion: x -> hi/lo, weights -> hi only --------
#define CONV_XBLKS 8192    // T*H/4/256
#define CONV_WBLKS 32768   // E*H*F/4/256
__global__ void convert_kernel(const float* __restrict__ x,
                               const float* __restrict__ w1,
                               const float* __restrict__ w3,
                               const float* __restrict__ w2) {
    long b = blockIdx.x;
    int tid = threadIdx.x;
    if (b < CONV_XBLKS) {
        size_t i = (size_t)b * 256 + tid;
        float4 v = ((const float4*)x)[i];
        uint32_t h0, l0, h1, l1;
        split2(v.x, v.y, h0, l0);
        split2(v.z, v.w, h1, l1);
        ((uint2*)g_xhi)[i] = make_uint2(h0, h1);
        ((uint2*)g_xlo)[i] = make_uint2(l0, l1);
    } else {
        b -= CONV_XBLKS;
        int w = (int)(b >> 15);
        size_t i = ((size_t)(b & 32767)) * 256 + tid;
        const float* src = (w == 0) ? w1 : (w == 1) ? w3 : w2;
        __half* dst = (w == 0) ? g_w1hi : (w == 1) ? g_w3hi : g_w2hi;
        float4 v = ((const float4*)src)[i];
        __half2 p0 = __floats2half2_rn(v.x, v.y);
        __half2 p1 = __floats2half2_rn(v.z, v.w);
        ((uint2*)dst)[i] = make_uint2(*(uint32_t*)&p0, *(uint32_t*)&p1);
    }
}

// ============================================================================
// GEMM1: gathered x[slot,:] @ {w1hi,w3hi} -> SwiGLU -> act hi/lo
// BM=128, BN=64 per matrix, BK=32, 8 warps (4m x 2n), 4-stage cp.async
// Stage: Ahi(10240) Alo(10240) B[2 mats](4608 ea) = 29696 B
// ============================================================================
#define G1_STAGE 29696
#define G1_SMEM (512 + 4 * G1_STAGE)

__global__ __launch_bounds__(256, 1) void gemm1_kernel() {
    const int mt = blockIdx.y;
    if (mt >= g_ntiles) return;
    extern __shared__ char smem[];
    int* rows = (int*)smem;
    const uint32_t sb = smem_u32(smem);
    const int tid = threadIdx.x;
    const int lane = tid & 31, wid = tid >> 5;
    const int e = g_tile_expert[mt];
    const int m0 = mt * BM;
    const int n0 = blockIdx.x * 64;

    if (tid < 128) rows[tid] = g_perm[m0 + tid];
    __syncthreads();

    // A loader: 2 threads per row, 32B each (hi and lo)
    const int ar = tid >> 1, ac0 = (tid & 1) * 2;
    const __half* srcAh = g_xhi + (size_t)rows[ar] * H_DIM + ac0 * 8;
    const __half* srcAl = g_xlo + (size_t)rows[ar] * H_DIM + ac0 * 8;
    // B loader: 128 threads per matrix, 32B each
    const int sel = tid >> 7;                   // matrix: 0=w1, 1=w3
    const int krow = tid & 31, chalf = (tid >> 5) & 3;
    const __half* wsrc0[2] = {g_w1hi + (size_t)e * H_DIM * F_DIM,
                              g_w3hi + (size_t)e * H_DIM * F_DIM};
    const __half* srcB = wsrc0[sel] + (size_t)krow * F_DIM + n0 + chalf * 16;
    const uint32_t dstA_h = (uint32_t)(ar * 80 + ac0 * 16);
    const uint32_t dstB = 20480u + (uint32_t)sel * 4608u + (uint32_t)(krow * 144 + chalf * 32);

    const int warpm = wid & 3, warpn = wid >> 2;
    const int m0w = warpm * 32, n0w = warpn * 32;

    float acc1[2][4][4], acc3[2][4][4];
#pragma unroll
    for (int mi = 0; mi < 2; mi++)
#pragma unroll
        for (int ni = 0; ni < 4; ni++)
#pragma unroll
            for (int r = 0; r < 4; r++) { acc1[mi][ni][r] = 0.f; acc3[mi][ni][r] = 0.f; }

#define G1_ISSUE(p)                                                              \
    {                                                                            \
        uint32_t st = sb + 512 + (uint32_t)((p) & 3) * G1_STAGE;                 \
        size_t k0 = (size_t)(p) * 32;                                            \
        cpa(st + dstA_h, srcAh + k0);                                            \
        cpa(st + dstA_h + 16, srcAh + k0 + 8);                                   \
        cpa(st + 10240 + dstA_h, srcAl + k0);                                    \
        cpa(st + 10240 + dstA_h + 16, srcAl + k0 + 8);                           \
        const __half* bs = srcB + k0 * F_DIM;                                    \
        cpa(st + dstB, bs);                                                      \
        cpa(st + dstB + 16, bs + 8);                                             \
    }

    G1_ISSUE(0); CP_COMMIT();
    G1_ISSUE(1); CP_COMMIT();
    G1_ISSUE(2); CP_COMMIT();

    const int a_lrow = (lane < 16) ? lane : (lane - 16);
    const int a_lkoff = (lane >= 16) ? 8 : 0;
    const int b_lk = ((lane >> 3) & 1) * 8 + (lane & 7);
    const int b_ln = (lane >> 4) * 8;

    for (int s = 0; s < NSTAGE; s++) {
        CP_WAIT2();
        __syncthreads();
        if (s + 3 < NSTAGE) { G1_ISSUE(s + 3); }
        CP_COMMIT();

        const uint32_t st = sb + 512 + (uint32_t)(s & 3) * G1_STAGE;
#pragma unroll
        for (int k16 = 0; k16 < 2; k16++) {
            const int kl = k16 * 16;
            uint32_t ahi[2][4], alo[2][4];
#pragma unroll
            for (int mi = 0; mi < 2; mi++) {
                uint32_t aaddr = st + (uint32_t)((m0w + mi * 16 + a_lrow) * 80 + (kl + a_lkoff) * 2);
                ldsm4(ahi[mi], aaddr);
                ldsm4(alo[mi], aaddr + 10240);
            }
            uint32_t B[2][4][2];  // [mat][ni][reg]
#pragma unroll
            for (int mat = 0; mat < 2; mat++)
#pragma unroll
                for (int nh = 0; nh < 2; nh++) {
                    uint32_t baddr = st + 20480u + (uint32_t)mat * 4608u +
                                     (uint32_t)((kl + b_lk) * 144 + (n0w + nh * 16 + b_ln) * 2);
                    uint32_t tmp[4];
                    ldsm4t(tmp, baddr);
                    B[mat][nh * 2 + 0][0] = tmp[0];
                    B[mat][nh * 2 + 0][1] = tmp[1];
                    B[mat][nh * 2 + 1][0] = tmp[2];
                    B[mat][nh * 2 + 1][1] = tmp[3];
                }
#pragma unroll
            for (int mi = 0; mi < 2; mi++)
#pragma unroll
                for (int ni = 0; ni < 4; ni++) {
                    mma16816(acc1[mi][ni], ahi[mi], B[0][ni]);
                    mma16816(acc1[mi][ni], alo[mi], B[0][ni]);
                    mma16816(acc3[mi][ni], ahi[mi], B[1][ni]);
                    mma16816(acc3[mi][ni], alo[mi], B[1][ni]);
                }
        }
        __syncthreads();
    }

    // epilogue: SwiGLU + split -> act hi/lo
    const int g = lane >> 2, tq = lane & 3;
#pragma unroll
    for (int mi = 0; mi < 2; mi++)
#pragma unroll
        for (int rp = 0; rp < 2; rp++) {
            const int slot = m0 + m0w + mi * 16 + rp * 8 + g;
#pragma unroll
            for (int ni = 0; ni < 4; ni++) {
                float h1a = acc1[mi][ni][rp * 2 + 0], h1b = acc1[mi][ni][rp * 2 + 1];
                float h3a = acc3[mi][ni][rp * 2 + 0], h3b = acc3[mi][ni][rp * 2 + 1];
                float va = h1a * h3a / (1.f + __expf(-h1a));
                float vb = h1b * h3b / (1.f + __expf(-h1b));
                uint32_t ph, pl;
                split2(va, vb, ph, pl);
                size_t o = (size_t)slot * F_DIM + n0 + n0w + ni * 8 + tq * 2;
                *(uint32_t*)((char*)g_acthi + o * 2) = ph;
                *(uint32_t*)((char*)g_actlo + o * 2) = pl;
            }
        }
}

// ============================================================================
// GEMM2: act(hi+lo) @ w2hi + weighted scatter-add. BM=128, BN=128, BK=32
// Stage: Ahi(10240) Alo(10240) B(8704) = 29184 B, 4 stages
// ============================================================================
#define G2_STAGE 29184
#define G2_SMEM (1024 + 4 * G2_STAGE)

__global__ __launch_bounds__(256, 1) void gemm2_kernel(float* __restrict__ out) {
    const int mt = blockIdx.y;
    if (mt >= g_ntiles) return;
    extern __shared__ char smem[];
    int* rows = (int*)smem;
    float* ws = (float*)(smem + 512);
    const uint32_t sb = smem_u32(smem);
    const int tid = threadIdx.x;
    const int lane = tid & 31, wid = tid >> 5;
    const int e = g_tile_expert[mt];
    const int m0 = mt * BM;
    const int n0 = blockIdx.x * 128;

    if (tid < 128) {
        rows[tid] = g_perm[m0 + tid];
        ws[tid] = g_slotw[m0 + tid];
    }
    __syncthreads();

    const int ar = tid >> 1, ac0 = (tid & 1) * 2;
    const __half* srcAh = g_acthi + (size_t)(m0 + ar) * F_DIM + ac0 * 8;
    const __half* srcAl = g_actlo + (size_t)(m0 + ar) * F_DIM + ac0 * 8;
    const int krow = tid & 31, cq = (tid >> 5) & 7;
    const __half* srcB = g_w2hi + (size_t)e * F_DIM * H_DIM + (size_t)krow * H_DIM + n0 + cq * 16;
    const uint32_t dstA_h = (uint32_t)(ar * 80 + ac0 * 16);
    const uint32_t dstB = 20480u + (uint32_t)(krow * 272 + cq * 32);

    const int warpm = wid & 3, warpn = wid >> 2;
    const int m0w = warpm * 32, n0w = warpn * 64;

    float acc[2][8][4];
#pragma unroll
    for (int mi = 0; mi < 2; mi++)
#pragma unroll
        for (int ni = 0; ni < 8; ni++)
#pragma unroll
            for (int r = 0; r < 4; r++) acc[mi][ni][r] = 0.f;

#define G2_ISSUE(p)                                                              \
    {                                                                            \
        uint32_t st = sb + 1024 + (uint32_t)((p) & 3) * G2_STAGE;                \
        size_t k0 = (size_t)(p) * 32;                                            \
        cpa(st + dstA_h, srcAh + k0);                                            \
        cpa(st + dstA_h + 16, srcAh + k0 + 8);                                   \
        cpa(st + 10240 + dstA_h, srcAl + k0);                                    \
        cpa(st + 10240 + dstA_h + 16, srcAl + k0 + 8);                           \
        const __half* bs = srcB + k0 * H_DIM;                                    \
        cpa(st + dstB, bs);                                                      \
        cpa(st + dstB + 16, bs + 8);                                             \
    }

    G2_ISSUE(0); CP_COMMIT();
    G2_ISSUE(1); CP_COMMIT();
    G2_ISSUE(2); CP_COMMIT();

    const int a_lrow = (lane < 16) ? lane : (lane - 16);
    const int a_lkoff = (lane >= 16) ? 8 : 0;
    const int b_lk = ((lane >> 3) & 1) * 8 + (lane & 7);
    const int b_ln = (lane >> 4) * 8;

    for (int s = 0; s < NSTAGE; s++) {
        CP_WAIT2();
        __syncthreads();
        if (s + 3 < NSTAGE) { G2_ISSUE(s + 3); }
        CP_COMMIT();

        const uint32_t st = sb + 1024 + (uint32_t)(s & 3) * G2_STAGE;
#pragma unroll
        for (int k16 = 0; k16 < 2; k16++) {
            const int kl = k16 * 16;
            uint32_t ahi[2][4], alo[2][4];
#pragma unroll
            for (int mi = 0; mi < 2; mi++) {
                uint32_t aaddr = st + (uint32_t)((m0w + mi * 16 + a_lrow) * 80 + (kl + a_lkoff) * 2);
                ldsm4(ahi[mi], aaddr);
                ldsm4(alo[mi], aaddr + 10240);
            }
            uint32_t B[8][2];
#pragma unroll
            for (int nh = 0; nh < 4; nh++) {
                uint32_t baddr = st + 20480u +
                                 (uint32_t)((kl + b_lk) * 272 + (n0w + nh * 16 + b_ln) * 2);
                uint32_t tmp[4];
                ldsm4t(tmp, baddr);
                B[nh * 2 + 0][0] = tmp[0];
                B[nh * 2 + 0][1] = tmp[1];
                B[nh * 2 + 1][0] = tmp[2];
                B[nh * 2 + 1][1] = tmp[3];
            }
#pragma unroll
            for (int mi = 0; mi < 2; mi++)
#pragma unroll
                for (int ni = 0; ni < 8; ni++) {
                    mma16816(acc[mi][ni], ahi[mi], B[ni]);
                    mma16816(acc[mi][ni], alo[mi], B[ni]);
                }
        }
        __syncthreads();
    }

    // epilogue: weighted scatter-add
    const int g = lane >> 2, tq = lane & 3;
#pragma unroll
    for (int mi = 0; mi < 2; mi++)
#pragma unroll
        for (int rp = 0; rp < 2; rp++) {
            const int rloc = m0w + mi * 16 + rp * 8 + g;
            const int tok = rows[rloc];
            const float wt = ws[rloc];
            if (wt != 0.f) {
                float* dst = out + (size_t)tok * H_DIM + n0 + n0w + tq * 2;
#pragma unroll
                for (int ni = 0; ni < 8; ni++) {
                    atomicAdd(dst + ni * 8 + 0, wt * acc[mi][ni][rp * 2 + 0]);
                    atomicAdd(dst + ni * 8 + 1, wt * acc[mi][ni][rp * 2 + 1]);
                }
            }
        }
}

// ---------------- launch ----------------------------------------------------
extern "C" void kernel_launch(void* const* d_in, const int* in_sizes, int n_in,
                              void* d_out, int out_size) {
    const float* x  = (const float*)d_in[0];
    const float* gw = (const float*)d_in[1];
    const float* w1 = (const float*)d_in[2];
    const float* w2 = (const float*)d_in[3];
    const float* w3 = (const float*)d_in[4];
    float* out = (float*)d_out;

    cudaFuncSetAttribute(gemm1_kernel, cudaFuncAttributeMaxDynamicSharedMemorySize, G1_SMEM);
    cudaFuncSetAttribute(gemm2_kernel, cudaFuncAttributeMaxDynamicSharedMemorySize, G2_SMEM);

    int n4 = (T_TOK * H_DIM) / 4;
    zero_kernel<<<(n4 + 255) / 256, 256>>>((float4*)out, n4);        // launch 0
    router_kernel<<<T_TOK / 8, 256>>>(x, gw);                        // launch 1
    assign_kernel<<<1, 256>>>();                                     // launch 2
    convert_kernel<<<CONV_XBLKS + 3 * CONV_WBLKS, 256>>>(x, w1, w3, w2);  // launch 3

    dim3 g1(F_DIM / 64, MAX_TILES);
    gemm1_kernel<<<g1, 256, G1_SMEM>>>();                            // launch 4
    dim3 g2(H_DIM / 128, MAX_TILES);
    gemm2_kernel<<<g2, 256, G2_SMEM>>>(out);                         // launch 5 (ncu -s 5)
}

// round 5
// speedup vs baseline: 5.0532x; 1.8385x over previous
#include <cuda_runtime.h>
#include <cuda_fp16.h>
#include <math.h>
#include <stdint.h>

// Problem constants: B=2,S=2048,H=2048,E=8,F=2048,top_k=2 (fp32 in/out)
#define T_TOK 4096
#define H_DIM 2048
#define E_NUM 8
#define F_DIM 2048

#define BM 128
#define MAX_TILES 72
#define MAX_SLOTS (T_TOK * 2 + E_NUM * BM)  // 9216
#define NST 32                               // K/64 stages

// ---------------- static device scratch (pure fp16 operands) ----------------
__device__ __half g_xh[(size_t)T_TOK * H_DIM];
__device__ __half g_w1h[(size_t)E_NUM * H_DIM * F_DIM];  // [E][H][F]
__device__ __half g_w3h[(size_t)E_NUM * H_DIM * F_DIM];
__device__ __half g_w2h[(size_t)E_NUM * F_DIM * H_DIM];  // [E][F][H]
__device__ __half g_act[(size_t)MAX_SLOTS * F_DIM];

__device__ int   g_perm[MAX_SLOTS];
__device__ float g_slotw[MAX_SLOTS];
__device__ int   g_topi[T_TOK * 2];
__device__ float g_topw[T_TOK * 2];
__device__ int   g_tile_expert[MAX_TILES];
__device__ int   g_ntiles;

// ---------------- PTX helpers (plain compute_103-legal) ---------------------
__device__ __forceinline__ uint32_t smem_u32(const void* p) {
    uint32_t a;
    asm("{ .reg .u64 t; cvta.to.shared.u64 t, %1; cvt.u32.u64 %0, t; }" : "=r"(a) : "l"(p));
    return a;
}
__device__ __forceinline__ void cpa(uint32_t dst, const void* src) {
    asm volatile("cp.async.cg.shared.global [%0], [%1], 16;" :: "r"(dst), "l"(src));
}
#define CP_COMMIT() asm volatile("cp.async.commit_group;" ::: "memory")
#define CP_WAIT1()  asm volatile("cp.async.wait_group 1;" ::: "memory")

__device__ __forceinline__ void ldsm4(uint32_t* r, uint32_t addr) {
    asm volatile("ldmatrix.sync.aligned.m8n8.x4.shared.b16 {%0,%1,%2,%3}, [%4];"
                 : "=r"(r[0]), "=r"(r[1]), "=r"(r[2]), "=r"(r[3]) : "r"(addr));
}
__device__ __forceinline__ void ldsm4t(uint32_t* r, uint32_t addr) {
    asm volatile("ldmatrix.sync.aligned.m8n8.x4.trans.shared.b16 {%0,%1,%2,%3}, [%4];"
                 : "=r"(r[0]), "=r"(r[1]), "=r"(r[2]), "=r"(r[3]) : "r"(addr));
}
__device__ __forceinline__ void mma16816(float* d, const uint32_t* a, const uint32_t* b) {
    asm volatile(
        "mma.sync.aligned.m16n8k16.row.col.f32.f16.f16.f32 "
        "{%0,%1,%2,%3}, {%4,%5,%6,%7}, {%8,%9}, {%0,%1,%2,%3};"
        : "+f"(d[0]), "+f"(d[1]), "+f"(d[2]), "+f"(d[3])
        : "r"(a[0]), "r"(a[1]), "r"(a[2]), "r"(a[3]), "r"(b[0]), "r"(b[1]));
}

// ---------------- zero output ----------------------------------------------
__global__ void zero_kernel(float4* out, int n4) {
    int i = blockIdx.x * blockDim.x + threadIdx.x;
    if (i < n4) out[i] = make_float4(0.f, 0.f, 0.f, 0.f);
}

// ---------------- router ---------------------------------------------------
__global__ void router_kernel(const float* __restrict__ x,
                              const float* __restrict__ gw) {
    int warp = threadIdx.x >> 5, lane = threadIdx.x & 31;
    int t = blockIdx.x * 8 + warp;
    if (t >= T_TOK) return;
    const float* xr = x + (size_t)t * H_DIM;
    float acc[E_NUM];
#pragma unroll
    for (int e = 0; e < E_NUM; e++) acc[e] = 0.f;
    for (int i = lane; i < H_DIM; i += 32) {
        float xv = xr[i];
#pragma unroll
        for (int e = 0; e < E_NUM; e++) acc[e] += xv * gw[e * H_DIM + i];
    }
#pragma unroll
    for (int e = 0; e < E_NUM; e++)
        for (int o = 16; o > 0; o >>= 1)
            acc[e] += __shfl_down_sync(0xffffffffu, acc[e], o);
    if (lane == 0) {
        float m = acc[0];
#pragma unroll
        for (int e = 1; e < E_NUM; e++) m = fmaxf(m, acc[e]);
        float p[E_NUM];
#pragma unroll
        for (int e = 0; e < E_NUM; e++) p[e] = expf(acc[e] - m);
        int a = 0;
#pragma unroll
        for (int e = 1; e < E_NUM; e++) if (p[e] > p[a]) a = e;
        int b = (a == 0) ? 1 : 0;
#pragma unroll
        for (int e = 0; e < E_NUM; e++)
            if (e != a && p[e] > p[b]) b = e;
        float denom = p[a] + p[b];
        g_topi[t * 2 + 0] = a;
        g_topi[t * 2 + 1] = b;
        g_topw[t * 2 + 0] = p[a] / denom;
        g_topw[t * 2 + 1] = p[b] / denom;
    }
}

// ---------------- assign ----------------------------------------------------
__global__ void assign_kernel() {
    __shared__ int cnt[E_NUM], cur[E_NUM], off[E_NUM], pcnt[E_NUM];
    int tid = threadIdx.x;
    if (tid < E_NUM) { cnt[tid] = 0; cur[tid] = 0; }
    __syncthreads();
    for (int i = tid; i < T_TOK * 2; i += blockDim.x)
        atomicAdd(&cnt[g_topi[i]], 1);
    __syncthreads();
    if (tid == 0) {
        int o = 0, mt = 0;
        for (int e = 0; e < E_NUM; e++) {
            off[e] = o;
            int pc = ((cnt[e] + BM - 1) / BM) * BM;
            pcnt[e] = pc;
            int tiles = pc / BM;
            for (int i = 0; i < tiles; i++) g_tile_expert[mt + i] = e;
            mt += tiles;
            o += pc;
        }
        g_ntiles = mt;
        for (int i = mt; i < MAX_TILES; i++) g_tile_expert[i] = 0;
    }
    __syncthreads();
    for (int i = tid; i < T_TOK * 2; i += blockDim.x) {
        int e = g_topi[i];
        int pos = off[e] + atomicAdd(&cur[e], 1);
        g_perm[pos] = i >> 1;
        g_slotw[pos] = g_topw[i];
    }
    __syncthreads();
    for (int j = tid; j < E_NUM * BM; j += blockDim.x) {
        int e = j / BM;
        int i = cnt[e] + (j % BM);
        if (i < pcnt[e]) {
            g_perm[off[e] + i] = 0;
            g_slotw[off[e] + i] = 0.f;
        }
    }
}

// ---------------- unified fp32 -> fp16 conversion ---------------------------
#define CONV_XBLKS 8192    // T*H/4/256
#define CONV_WBLKS 32768   // E*H*F/4/256
__global__ void convert_kernel(const float* __restrict__ x,
                               const float* __restrict__ w1,
                               const float* __restrict__ w3,
                               const float* __restrict__ w2) {
    long b = blockIdx.x;
    int tid = threadIdx.x;
    const float* src;
    __half* dst;
    size_t i;
    if (b < CONV_XBLKS) {
        src = x; dst = g_xh;
        i = (size_t)b * 256 + tid;
    } else {
        b -= CONV_XBLKS;
        int w = (int)(b >> 15);
        i = ((size_t)(b & 32767)) * 256 + tid;
        src = (w == 0) ? w1 : (w == 1) ? w3 : w2;
        dst = (w == 0) ? g_w1h : (w == 1) ? g_w3h : g_w2h;
    }
    float4 v = ((const float4*)src)[i];
    __half2 p0 = __floats2half2_rn(v.x, v.y);
    __half2 p1 = __floats2half2_rn(v.z, v.w);
    ((uint2*)dst)[i] = make_uint2(*(uint32_t*)&p0, *(uint32_t*)&p1);
}

// ============================================================================
// GEMM1: gathered x[slot,:] @ {w1,w3} -> SwiGLU -> act (fp16)
// BM=128, BN=64 per matrix, BK=64, 8 warps (4m x 2n), 3-stage cp.async
// Stage: A 128x144B = 18432 | B 2 x 64x144B = 18432  -> 36864 B
// ============================================================================
#define G1_STAGE 36864
#define G1_SMEM (512 + 3 * G1_STAGE)

__global__ __launch_bounds__(256, 1) void gemm1_kernel() {
    const int mt = blockIdx.y;
    if (mt >= g_ntiles) return;
    extern __shared__ char smem[];
    int* rows = (int*)smem;
    const uint32_t sb = smem_u32(smem);
    const int tid = threadIdx.x;
    const int lane = tid & 31, wid = tid >> 5;
    const int e = g_tile_expert[mt];
    const int m0 = mt * BM;
    const int n0 = blockIdx.x * 64;

    if (tid < 128) rows[tid] = g_perm[m0 + tid];
    __syncthreads();

    // A loader: 4 rows per thread (tid>>3 + t*32), 16B chunk q per row
    const uint32_t q = (uint32_t)(tid & 7) * 16;  // byte offset within 128B row
    const char* srcA[4];
    uint32_t dA[4];
#pragma unroll
    for (int t = 0; t < 4; t++) {
        int r = (tid >> 3) + t * 32;
        srcA[t] = (const char*)(g_xh + (size_t)rows[r] * H_DIM) + q;
        dA[t] = (uint32_t)r * 144 + q;
    }
    // B loader: per t: mat = t>>1, krow = (tid>>3) + (t&1)*32
    const char* wbase[2] = {(const char*)(g_w1h + (size_t)e * H_DIM * F_DIM),
                            (const char*)(g_w3h + (size_t)e * H_DIM * F_DIM)};
    const int krow_b = tid >> 3;

    const int warpm = wid & 3, warpn = wid >> 2;
    const int m0w = warpm * 32, n0w = warpn * 32;

    float acc1[2][4][4], acc3[2][4][4];
#pragma unroll
    for (int mi = 0; mi < 2; mi++)
#pragma unroll
        for (int ni = 0; ni < 4; ni++)
#pragma unroll
            for (int r = 0; r < 4; r++) { acc1[mi][ni][r] = 0.f; acc3[mi][ni][r] = 0.f; }

#define G1_ISSUE(p)                                                               \
    {                                                                             \
        uint32_t st = sb + 512 + (uint32_t)((p) % 3) * G1_STAGE;                  \
        size_t kb = (size_t)(p) * 64 * 2; /* bytes along K of A row */            \
        cpa(st + dA[0], srcA[0] + kb);                                            \
        cpa(st + dA[1], srcA[1] + kb);                                            \
        cpa(st + dA[2], srcA[2] + kb);                                            \
        cpa(st + dA[3], srcA[3] + kb);                                            \
        _Pragma("unroll")                                                         \
        for (int t = 0; t < 4; t++) {                                             \
            int mat = t >> 1;                                                     \
            int kr = krow_b + (t & 1) * 32;                                       \
            const char* bs = wbase[mat] +                                         \
                (((size_t)(p) * 64 + kr) * F_DIM + n0) * 2 + q;                   \
            cpa(st + 18432u + (uint32_t)mat * 9216u + (uint32_t)kr * 144 + q, bs);\
        }                                                                         \
    }

    G1_ISSUE(0); CP_COMMIT();
    G1_ISSUE(1); CP_COMMIT();

    const int a_lrow = (lane < 16) ? lane : (lane - 16);
    const int a_lkoff = (lane >= 16) ? 8 : 0;
    const int b_lk = ((lane >> 3) & 1) * 8 + (lane & 7);
    const int b_ln = (lane >> 4) * 8;

    for (int s = 0; s < NST; s++) {
        CP_WAIT1();
        __syncthreads();
        if (s + 2 < NST) { G1_ISSUE(s + 2); }
        CP_COMMIT();

        const uint32_t st = sb + 512 + (uint32_t)(s % 3) * G1_STAGE;
#pragma unroll
        for (int k16 = 0; k16 < 4; k16++) {
            const int kl = k16 * 16;
            uint32_t a[2][4];
#pragma unroll
            for (int mi = 0; mi < 2; mi++)
                ldsm4(a[mi], st + (uint32_t)((m0w + mi * 16 + a_lrow) * 144 + (kl + a_lkoff) * 2));
            uint32_t B[2][4][2];
#pragma unroll
            for (int mat = 0; mat < 2; mat++)
#pragma unroll
                for (int nh = 0; nh < 2; nh++) {
                    uint32_t baddr = st + 18432u + (uint32_t)mat * 9216u +
                                     (uint32_t)((kl + b_lk) * 144 + (n0w + nh * 16 + b_ln) * 2);
                    uint32_t tmp[4];
                    ldsm4t(tmp, baddr);
                    B[mat][nh * 2 + 0][0] = tmp[0];
                    B[mat][nh * 2 + 0][1] = tmp[1];
                    B[mat][nh * 2 + 1][0] = tmp[2];
                    B[mat][nh * 2 + 1][1] = tmp[3];
                }
#pragma unroll
            for (int mi = 0; mi < 2; mi++)
#pragma unroll
                for (int ni = 0; ni < 4; ni++) {
                    mma16816(acc1[mi][ni], a[mi], B[0][ni]);
                    mma16816(acc3[mi][ni], a[mi], B[1][ni]);
                }
        }
        __syncthreads();
    }

    // epilogue: SwiGLU -> fp16 act
    const int g = lane >> 2, tq = lane & 3;
#pragma unroll
    for (int mi = 0; mi < 2; mi++)
#pragma unroll
        for (int rp = 0; rp < 2; rp++) {
            const int slot = m0 + m0w + mi * 16 + rp * 8 + g;
#pragma unroll
            for (int ni = 0; ni < 4; ni++) {
                float h1a = acc1[mi][ni][rp * 2 + 0], h1b = acc1[mi][ni][rp * 2 + 1];
                float h3a = acc3[mi][ni][rp * 2 + 0], h3b = acc3[mi][ni][rp * 2 + 1];
                float va = h1a * h3a / (1.f + __expf(-h1a));
                float vb = h1b * h3b / (1.f + __expf(-h1b));
                __half2 pk = __floats2half2_rn(va, vb);
                size_t o = (size_t)slot * F_DIM + n0 + n0w + ni * 8 + tq * 2;
                *(uint32_t*)((char*)g_act + o * 2) = *(uint32_t*)&pk;
            }
        }
}

// ============================================================================
// GEMM2: act @ w2 + weighted scatter-add. BM=128, BN=128, BK=64
// Stage: A 128x144B = 18432 | B 64x272B = 17408  -> 35840 B
// ============================================================================
#define G2_STAGE 35840
#define G2_SMEM (1024 + 3 * G2_STAGE)

__global__ __launch_bounds__(256, 1) void gemm2_kernel(float* __restrict__ out) {
    const int mt = blockIdx.y;
    if (mt >= g_ntiles) return;
    extern __shared__ char smem[];
    int* rows = (int*)smem;
    float* ws = (float*)(smem + 512);
    const uint32_t sb = smem_u32(smem);
    const int tid = threadIdx.x;
    const int lane = tid & 31, wid = tid >> 5;
    const int e = g_tile_expert[mt];
    const int m0 = mt * BM;
    const int n0 = blockIdx.x * 128;

    if (tid < 128) {
        rows[tid] = g_perm[m0 + tid];
        ws[tid] = g_slotw[m0 + tid];
    }
    __syncthreads();

    // A loader: 4 rows per thread, contiguous act rows
    const uint32_t qa = (uint32_t)(tid & 7) * 16;
    const int ra = tid >> 3;
    const char* srcA = (const char*)(g_act + (size_t)(m0 + ra) * F_DIM) + qa;
    // B loader: 4 rows per thread of 256B rows: krow = (tid>>4) + t*16, q 16B
    const uint32_t qb = (uint32_t)(tid & 15) * 16;
    const int rb = tid >> 4;
    const char* srcB = (const char*)(g_w2h + (size_t)e * F_DIM * H_DIM + n0) + qb;

    const int warpm = wid & 3, warpn = wid >> 2;
    const int m0w = warpm * 32, n0w = warpn * 64;

    float acc[2][8][4];
#pragma unroll
    for (int mi = 0; mi < 2; mi++)
#pragma unroll
        for (int ni = 0; ni < 8; ni++)
#pragma unroll
            for (int r = 0; r < 4; r++) acc[mi][ni][r] = 0.f;

#define G2_ISSUE(p)                                                               \
    {                                                                             \
        uint32_t st = sb + 1024 + (uint32_t)((p) % 3) * G2_STAGE;                 \
        size_t kb = (size_t)(p) * 64 * 2;                                         \
        _Pragma("unroll")                                                         \
        for (int t = 0; t < 4; t++) {                                             \
            int r = ra + t * 32;                                                  \
            cpa(st + (uint32_t)r * 144 + qa,                                      \
                srcA + (size_t)t * 32 * F_DIM * 2 + kb);                          \
        }                                                                         \
        _Pragma("unroll")                                                         \
        for (int t = 0; t < 4; t++) {                                             \
            int kr = rb + t * 16;                                                 \
            cpa(st + 18432u + (uint32_t)kr * 272 + qb,                            \
                srcB + ((size_t)(p) * 64 + kr) * H_DIM * 2);                      \
        }                                                                         \
    }

    G2_ISSUE(0); CP_COMMIT();
    G2_ISSUE(1); CP_COMMIT();

    const int a_lrow = (lane < 16) ? lane : (lane - 16);
    const int a_lkoff = (lane >= 16) ? 8 : 0;
    const int b_lk = ((lane >> 3) & 1) * 8 + (lane & 7);
    const int b_ln = (lane >> 4) * 8;

    for (int s = 0; s < NST; s++) {
        CP_WAIT1();
        __syncthreads();
        if (s + 2 < NST) { G2_ISSUE(s + 2); }
        CP_COMMIT();

        const uint32_t st = sb + 1024 + (uint32_t)(s % 3) * G2_STAGE;
#pragma unroll
        for (int k16 = 0; k16 < 4; k16++) {
            const int kl = k16 * 16;
            uint32_t a[2][4];
#pragma unroll
            for (int mi = 0; mi < 2; mi++)
                ldsm4(a[mi], st + (uint32_t)((m0w + mi * 16 + a_lrow) * 144 + (kl + a_lkoff) * 2));
            uint32_t B[8][2];
#pragma unroll
            for (int nh = 0; nh < 4; nh++) {
                uint32_t baddr = st + 18432u +
                                 (uint32_t)((kl + b_lk) * 272 + (n0w + nh * 16 + b_ln) * 2);
                uint32_t tmp[4];
                ldsm4t(tmp, baddr);
                B[nh * 2 + 0][0] = tmp[0];
                B[nh * 2 + 0][1] = tmp[1];
                B[nh * 2 + 1][0] = tmp[2];
                B[nh * 2 + 1][1] = tmp[3];
            }
#pragma unroll
            for (int mi = 0; mi < 2; mi++)
#pragma unroll
                for (int ni = 0; ni < 8; ni++)
                    mma16816(acc[mi][ni], a[mi], B[ni]);
        }
        __syncthreads();
    }

    // epilogue: weighted scatter-add
    const int g = lane >> 2, tq = lane & 3;
#pragma unroll
    for (int mi = 0; mi < 2; mi++)
#pragma unroll
        for (int rp = 0; rp < 2; rp++) {
            const int rloc = m0w + mi * 16 + rp * 8 + g;
            const int tok = rows[rloc];
            const float wt = ws[rloc];
            if (wt != 0.f) {
                float* dst = out + (size_t)tok * H_DIM + n0 + n0w + tq * 2;
#pragma unroll
                for (int ni = 0; ni < 8; ni++) {
                    atomicAdd(dst + ni * 8 + 0, wt * acc[mi][ni][rp * 2 + 0]);
                    atomicAdd(dst + ni * 8 + 1, wt * acc[mi][ni][rp * 2 + 1]);
                }
            }
        }
}

// ---------------- launch ----------------------------------------------------
extern "C" void kernel_launch(void* const* d_in, const int* in_sizes, int n_in,
                              void* d_out, int out_size) {
    const float* x  = (const float*)d_in[0];
    const float* gw = (const float*)d_in[1];
    const float* w1 = (const float*)d_in[2];
    const float* w2 = (const float*)d_in[3];
    const float* w3 = (const float*)d_in[4];
    float* out = (float*)d_out;

    cudaFuncSetAttribute(gemm1_kernel, cudaFuncAttributeMaxDynamicSharedMemorySize, G1_SMEM);
    cudaFuncSetAttribute(gemm2_kernel, cudaFuncAttributeMaxDynamicSharedMemorySize, G2_SMEM);

    int n4 = (T_TOK * H_DIM) / 4;
    zero_kernel<<<(n4 + 255) / 256, 256>>>((float4*)out, n4);
    router_kernel<<<T_TOK / 8, 256>>>(x, gw);
    assign_kernel<<<1, 256>>>();
    convert_kernel<<<CONV_XBLKS + 3 * CONV_WBLKS, 256>>>(x, w1, w3, w2);

    dim3 g1(F_DIM / 64, MAX_TILES);
    gemm1_kernel<<<g1, 256, G1_SMEM>>>();
    dim3 g2(H_DIM / 128, MAX_TILES);
    gemm2_kernel<<<g2, 256, G2_SMEM>>>(out);
}